// round 16
// baseline (speedup 1.0000x reference)
#include <cuda_runtime.h>
#include <math.h>

typedef unsigned long long u64;

// ---------------- device scratch (no allocations allowed) ----------------
__device__ float g_pool[512];   // [B=8][C=64] global average pool
__device__ float g_coef[4];     // per-expert mixture coefficient

// ---------------- packed fp32x2 FMA (Blackwell FFMA2) ----------------
__device__ __forceinline__ u64 ffma2(u64 a, u64 b, u64 c) {
    u64 d;
    asm("fma.rn.f32x2 %0, %1, %2, %3;" : "=l"(d) : "l"(a), "l"(b), "l"(c));
    return d;
}
__device__ __forceinline__ float2 u2f(u64 v) {
    float2 r;
    r.x = __uint_as_float((unsigned)(v & 0xffffffffull));
    r.y = __uint_as_float((unsigned)(v >> 32));
    return r;
}

// ---------------- 1) global average pool: one block per (b,c) plane ----------------
__global__ void avgpool_kernel(const float* __restrict__ x) {
    const int plane = blockIdx.x;                       // b*64 + c
    const float4* p = reinterpret_cast<const float4*>(x + (size_t)plane * 65536);
    float s = 0.0f;
    for (int i = threadIdx.x; i < 16384; i += 256) {
        float4 v = p[i];
        s += (v.x + v.y) + (v.z + v.w);
    }
    __shared__ float red[256];
    red[threadIdx.x] = s;
    __syncthreads();
    for (int st = 128; st > 0; st >>= 1) {
        if (threadIdx.x < st) red[threadIdx.x] += red[threadIdx.x + st];
        __syncthreads();
    }
    if (threadIdx.x == 0) g_pool[plane] = red[0] * (1.0f / 65536.0f);
}

// ---------------- 2) gating network in fp64 (tiny, precision-critical) ----------------
__global__ void gating_kernel(const float* __restrict__ gw1, const float* __restrict__ gb1,
                              const float* __restrict__ gw2, const float* __restrict__ gb2,
                              float* __restrict__ lossOut) {
    __shared__ float  gs[512];          // pooled features
    __shared__ double hid[8][512];      // hidden activations
    __shared__ double part[8][4][8];    // partial logit sums
    __shared__ double lg[8][4];         // pre-softmax logits
    const int t = threadIdx.x;          // 256 threads

    if (t < 256) { gs[t] = g_pool[t]; gs[t + 256] = g_pool[t + 256]; }
    __syncthreads();

    // hidden layer: hid[b][h] = relu(gb1[h] + sum_c gw1[h][c]*g[b][c])
    for (int h = t; h < 512; h += 256) {
        for (int b = 0; b < 8; b++) {
            double acc = (double)gb1[h];
            for (int c = 0; c < 64; c++)
                acc += (double)gw1[h * 64 + c] * (double)gs[b * 64 + c];
            hid[b][h] = acc > 0.0 ? acc : 0.0;
        }
    }
    __syncthreads();

    // logits: split the 512-sum into 8 segments per (b,e)
    {
        const int b = t >> 5, e = (t >> 3) & 3, s = t & 7;
        double acc = 0.0;
        const int h0 = s * 64;
        for (int h = h0; h < h0 + 64; h++)
            acc += (double)gw2[e * 512 + h] * hid[b][h];
        part[b][e][s] = acc;
    }
    __syncthreads();
    if (t < 32) {
        const int b = t >> 2, e = t & 3;
        double acc = (double)gb2[e];
        for (int s = 0; s < 8; s++) acc += part[b][e][s];
        lg[b][e] = acc;
    }
    __syncthreads();

    if (t == 0) {
        double sm[32];
        for (int b = 0; b < 8; b++) {
            double mx = lg[b][0];
            for (int e = 1; e < 4; e++) if (lg[b][e] > mx) mx = lg[b][e];
            double s = 0.0;
            for (int e = 0; e < 4; e++) { double v = exp(lg[b][e] - mx); sm[b * 4 + e] = v; s += v; }
            for (int e = 0; e < 4; e++) sm[b * 4 + e] /= s;
        }
        // loss = std(ddof=1) / (mean + eps) * 0.1 over all 32 softmax values
        double sum = 0.0;
        for (int i = 0; i < 32; i++) sum += sm[i];
        const double mean = sum / 32.0;
        double var = 0.0;
        for (int i = 0; i < 32; i++) { double d = sm[i] - mean; var += d * d; }
        var /= 31.0;
        const double loss = sqrt(var) / (mean + 1e-10) * 0.1;

        // top-2 per batch (ties -> lower index), softmax over the 2, scatter-add
        float coef[4] = {0.f, 0.f, 0.f, 0.f};
        for (int b = 0; b < 8; b++) {
            const double* v = sm + b * 4;
            int i1 = 0;
            for (int e = 1; e < 4; e++) if (v[e] > v[i1]) i1 = e;
            int i2 = (i1 == 0) ? 1 : 0;
            for (int e = 0; e < 4; e++) if (e != i1 && v[e] > v[i2]) i2 = e;
            const double m = v[i1] > v[i2] ? v[i1] : v[i2];
            const double e1 = exp(v[i1] - m), e2 = exp(v[i2] - m);
            const double s = e1 + e2;
            coef[i1] += (float)(e1 / s);
            coef[i2] += (float)(e2 / s);
        }
        for (int e = 0; e < 4; e++) g_coef[e] = coef[e];
        lossOut[0] = (float)loss;
    }
}

// ---------------- 3) expert conv + sigmoid + scaled accumulate ----------------
// Block: 16x16 output pixels x 32 output channels. 256 threads:
//   cg   = t>>5  (0..7)  -> 4 output channels: coBase + cg*4 + {0,1,2,3}
//   row  = (t>>1)&15     -> output row within tile
//   half = t&1           -> 8-pixel column half
// Accumulators: 8 pixels x 2 co-pairs, packed f32x2 (co even/odd in lo/hi).
// Input tile stored as duplicated (v,v) float2 so the FMA2 'a' operand is one LDS.64.
template <int K, int CICH>
__global__ void __launch_bounds__(256, 2)
conv_expert(const float* __restrict__ x, const float* __restrict__ w,
            const float* __restrict__ bias, int eIdx,
            float* __restrict__ out, int first)
{
    constexpr int PAD  = K / 2;
    constexpr int PH   = 16 + K - 1;
    constexpr int PW   = 16 + K - 1;
    constexpr int PWS  = (PW % 2 == 0) ? PW + 1 : PW;   // odd pair-stride -> conflict-free
    constexpr int KK   = K * K;
    constexpr int NWIN = 8 + K - 1;

    __shared__ float2 sIn[CICH][PH][PWS];   // duplicated (v,v) pairs
    __shared__ float2 sW[CICH][KK][17];     // 16 co-pairs + pad (stride 17 pairs)

    const float coef = g_coef[eIdx];
    if (!first && coef == 0.0f) return;     // expert never selected -> no-op

    const int t       = threadIdx.x;
    const int b       = blockIdx.z >> 1;
    const int coBase  = (blockIdx.z & 1) * 32;
    const int tileY   = blockIdx.y * 16;
    const int tileX   = blockIdx.x * 16;

    const int cg      = t >> 5;         // warp-uniform
    const int row     = (t >> 1) & 15;
    const int half    = t & 1;
    const int colBase = half * 8;

    u64 acc[8][2];
#pragma unroll
    for (int p = 0; p < 8; p++) { acc[p][0] = 0ull; acc[p][1] = 0ull; }

    const float* xb = x + (size_t)b * 64 * 65536;

    for (int ciBase = 0; ciBase < 64; ciBase += CICH) {
        __syncthreads();
        // ---- stage input tile (zero-padded, duplicated pairs) ----
        for (int i = t; i < CICH * PH * PW; i += 256) {
            const int cc  = i / (PH * PW);
            const int rem = i - cc * (PH * PW);
            const int r   = rem / PW;
            const int c   = rem - r * PW;
            const int gy  = tileY + r - PAD;
            const int gx  = tileX + c - PAD;
            float v = 0.0f;
            if ((unsigned)gy < 256u && (unsigned)gx < 256u)
                v = xb[(size_t)(ciBase + cc) * 65536 + gy * 256 + gx];
            sIn[cc][r][c] = make_float2(v, v);
        }
        // ---- stage weights as co-pairs: sW[cc][q][cp] = (w[co_even], w[co_odd]) ----
        for (int i = t; i < CICH * 16 * KK; i += 256) {
            const int q   = i % KK;
            const int cp  = (i / KK) & 15;
            const int cc  = i / (16 * KK);
            const int co0 = coBase + 2 * cp;
            const float* wp = w + ((size_t)co0 * 64 + (ciBase + cc)) * KK + q;
            sW[cc][q][cp] = make_float2(wp[0], wp[64 * KK]);
        }
        __syncthreads();

        // ---- compute ----
        for (int cc = 0; cc < CICH; cc++) {
#pragma unroll 1
            for (int dy = 0; dy < K; dy++) {
                u64 win[NWIN];
#pragma unroll
                for (int i = 0; i < NWIN; i++)
                    win[i] = *reinterpret_cast<const u64*>(&sIn[cc][row + dy][colBase + i]);
#pragma unroll
                for (int dx = 0; dx < K; dx++) {
                    const u64 w0 = *reinterpret_cast<const u64*>(&sW[cc][dy * K + dx][cg * 2 + 0]);
                    const u64 w1 = *reinterpret_cast<const u64*>(&sW[cc][dy * K + dx][cg * 2 + 1]);
#pragma unroll
                    for (int p = 0; p < 8; p++) {
                        acc[p][0] = ffma2(win[p + dx], w0, acc[p][0]);
                        acc[p][1] = ffma2(win[p + dx], w1, acc[p][1]);
                    }
                }
            }
        }
    }

    // ---- epilogue: bias -> sigmoid -> out (+=) coef * attn * x ----
    const int gy     = tileY + row;
    const int gxBase = tileX + colBase;
#pragma unroll
    for (int cp = 0; cp < 2; cp++) {
#pragma unroll
        for (int j = 0; j < 2; j++) {
            const int co = coBase + cg * 4 + cp * 2 + j;
            const float bv = bias[co];
            const size_t base = ((size_t)(b * 64 + co) * 256 + gy) * 256 + gxBase;
            float xs[8], os[8], rs[8];
            *reinterpret_cast<float4*>(xs)     = *reinterpret_cast<const float4*>(x + base);
            *reinterpret_cast<float4*>(xs + 4) = *reinterpret_cast<const float4*>(x + base + 4);
            if (first) {
#pragma unroll
                for (int p = 0; p < 8; p++) os[p] = 0.0f;
            } else {
                *reinterpret_cast<float4*>(os)     = *reinterpret_cast<const float4*>(out + base);
                *reinterpret_cast<float4*>(os + 4) = *reinterpret_cast<const float4*>(out + base + 4);
            }
#pragma unroll
            for (int p = 0; p < 8; p++) {
                const float2 a = u2f(acc[p][cp]);
                const float y = (j == 0 ? a.x : a.y) + bv;
                const float attn = 1.0f / (1.0f + __expf(-y));
                rs[p] = os[p] + coef * (attn * xs[p]);
            }
            *reinterpret_cast<float4*>(out + base)     = *reinterpret_cast<const float4*>(rs);
            *reinterpret_cast<float4*>(out + base + 4) = *reinterpret_cast<const float4*>(rs + 4);
        }
    }
}

// ---------------- launcher ----------------
extern "C" void kernel_launch(void* const* d_in, const int* in_sizes, int n_in,
                              void* d_out, int out_size) {
    (void)in_sizes; (void)n_in;
    const float* x    = (const float*)d_in[0];
    const float* gw1  = (const float*)d_in[1];
    const float* gb1  = (const float*)d_in[2];
    const float* gw2  = (const float*)d_in[3];
    const float* gb2  = (const float*)d_in[4];
    const float* ew1  = (const float*)d_in[5];
    const float* eb1  = (const float*)d_in[6];
    const float* ew3  = (const float*)d_in[7];
    const float* eb3  = (const float*)d_in[8];
    const float* ew7  = (const float*)d_in[9];
    const float* eb7  = (const float*)d_in[10];
    const float* ew11 = (const float*)d_in[11];
    const float* eb11 = (const float*)d_in[12];
    float* out = (float*)d_out;

    // Output layout: [8,64,256,256] tensor = 33,554,432 floats, then the scalar
    // loss as the LAST element. Use out_size so the offset can't be wrong again.
    float* lossPtr = out + (size_t)(out_size - 1);

    avgpool_kernel<<<512, 256>>>(x);
    gating_kernel<<<1, 256>>>(gw1, gb1, gw2, gb2, lossPtr);

    dim3 grid(16, 16, 16);  // (W/16, H/16, B * 2 co-halves)
    conv_expert<1, 16><<<grid, 256>>>(x, ew1,  eb1,  0, out, 1);
    conv_expert<3,  8><<<grid, 256>>>(x, ew3,  eb3,  1, out, 0);
    conv_expert<7,  4><<<grid, 256>>>(x, ew7,  eb7,  2, out, 0);
    conv_expert<11, 2><<<grid, 256>>>(x, ew11, eb11, 3, out, 0);
}

// round 17
// speedup vs baseline: 1.0005x; 1.0005x over previous
#include <cuda_runtime.h>
#include <math.h>

typedef unsigned long long u64;

// ---------------- device scratch (no allocations allowed) ----------------
__device__ float g_pool[512];   // [B=8][C=64] global average pool
__device__ float g_coef[4];     // per-expert mixture coefficient

// ---------------- packed fp32x2 FMA (Blackwell FFMA2) ----------------
__device__ __forceinline__ u64 ffma2(u64 a, u64 b, u64 c) {
    u64 d;
    asm("fma.rn.f32x2 %0, %1, %2, %3;" : "=l"(d) : "l"(a), "l"(b), "l"(c));
    return d;
}
__device__ __forceinline__ float2 u2f(u64 v) {
    float2 r;
    r.x = __uint_as_float((unsigned)(v & 0xffffffffull));
    r.y = __uint_as_float((unsigned)(v >> 32));
    return r;
}

// ---------------- 1) global average pool: one block per (b,c) plane ----------------
__global__ void avgpool_kernel(const float* __restrict__ x) {
    const int plane = blockIdx.x;                       // b*64 + c
    const float4* p = reinterpret_cast<const float4*>(x + (size_t)plane * 65536);
    float s = 0.0f;
    for (int i = threadIdx.x; i < 16384; i += 256) {
        float4 v = p[i];
        s += (v.x + v.y) + (v.z + v.w);
    }
    __shared__ float red[256];
    red[threadIdx.x] = s;
    __syncthreads();
    for (int st = 128; st > 0; st >>= 1) {
        if (threadIdx.x < st) red[threadIdx.x] += red[threadIdx.x + st];
        __syncthreads();
    }
    if (threadIdx.x == 0) g_pool[plane] = red[0] * (1.0f / 65536.0f);
}

// ---------------- 2) gating network in fp64 (tiny, precision-critical) ----------------
__global__ void gating_kernel(const float* __restrict__ gw1, const float* __restrict__ gb1,
                              const float* __restrict__ gw2, const float* __restrict__ gb2,
                              float* __restrict__ lossOut) {
    __shared__ float  gs[512];          // pooled features
    __shared__ double hid[8][512];      // hidden activations
    __shared__ double part[8][4][8];    // partial logit sums
    __shared__ double lg[8][4];         // pre-softmax logits
    const int t = threadIdx.x;          // 256 threads

    if (t < 256) { gs[t] = g_pool[t]; gs[t + 256] = g_pool[t + 256]; }
    __syncthreads();

    // hidden layer: hid[b][h] = relu(gb1[h] + sum_c gw1[h][c]*g[b][c])
    for (int h = t; h < 512; h += 256) {
        for (int b = 0; b < 8; b++) {
            double acc = (double)gb1[h];
            for (int c = 0; c < 64; c++)
                acc += (double)gw1[h * 64 + c] * (double)gs[b * 64 + c];
            hid[b][h] = acc > 0.0 ? acc : 0.0;
        }
    }
    __syncthreads();

    // logits: split the 512-sum into 8 segments per (b,e)
    {
        const int b = t >> 5, e = (t >> 3) & 3, s = t & 7;
        double acc = 0.0;
        const int h0 = s * 64;
        for (int h = h0; h < h0 + 64; h++)
            acc += (double)gw2[e * 512 + h] * hid[b][h];
        part[b][e][s] = acc;
    }
    __syncthreads();
    if (t < 32) {
        const int b = t >> 2, e = t & 3;
        double acc = (double)gb2[e];
        for (int s = 0; s < 8; s++) acc += part[b][e][s];
        lg[b][e] = acc;
    }
    __syncthreads();

    if (t == 0) {
        double sm[32];
        for (int b = 0; b < 8; b++) {
            double mx = lg[b][0];
            for (int e = 1; e < 4; e++) if (lg[b][e] > mx) mx = lg[b][e];
            double s = 0.0;
            for (int e = 0; e < 4; e++) { double v = exp(lg[b][e] - mx); sm[b * 4 + e] = v; s += v; }
            for (int e = 0; e < 4; e++) sm[b * 4 + e] /= s;
        }
        // loss = std(ddof=1) / (mean + eps) * 0.1 over all 32 softmax values
        double sum = 0.0;
        for (int i = 0; i < 32; i++) sum += sm[i];
        const double mean = sum / 32.0;
        double var = 0.0;
        for (int i = 0; i < 32; i++) { double d = sm[i] - mean; var += d * d; }
        var /= 31.0;
        const double loss = sqrt(var) / (mean + 1e-10) * 0.1;

        // top-2 per batch (ties -> lower index), softmax over the 2, scatter-add
        float coef[4] = {0.f, 0.f, 0.f, 0.f};
        for (int b = 0; b < 8; b++) {
            const double* v = sm + b * 4;
            int i1 = 0;
            for (int e = 1; e < 4; e++) if (v[e] > v[i1]) i1 = e;
            int i2 = (i1 == 0) ? 1 : 0;
            for (int e = 0; e < 4; e++) if (e != i1 && v[e] > v[i2]) i2 = e;
            const double m = v[i1] > v[i2] ? v[i1] : v[i2];
            const double e1 = exp(v[i1] - m), e2 = exp(v[i2] - m);
            const double s = e1 + e2;
            coef[i1] += (float)(e1 / s);
            coef[i2] += (float)(e2 / s);
        }
        for (int e = 0; e < 4; e++) g_coef[e] = coef[e];
        lossOut[0] = (float)loss;
    }
}

// ---------------- 3) expert conv + sigmoid + scaled accumulate ----------------
// Block: 16x16 output pixels x 32 output channels. 256 threads:
//   cg   = t>>5  (0..7)  -> 4 output channels: coBase + cg*4 + {0,1,2,3}
//   row  = (t>>1)&15     -> output row within tile
//   half = t&1           -> 8-pixel column half
// Accumulators: 8 pixels x 2 co-pairs, packed f32x2 (co even/odd in lo/hi).
// Input tile stored as duplicated (v,v) float2 so the FMA2 'a' operand is one LDS.64.
template <int K, int CICH>
__global__ void __launch_bounds__(256, 2)
conv_expert(const float* __restrict__ x, const float* __restrict__ w,
            const float* __restrict__ bias, int eIdx,
            float* __restrict__ out, int first)
{
    constexpr int PAD  = K / 2;
    constexpr int PH   = 16 + K - 1;
    constexpr int PW   = 16 + K - 1;
    constexpr int PWS  = (PW % 2 == 0) ? PW + 1 : PW;   // odd pair-stride -> conflict-free
    constexpr int KK   = K * K;
    constexpr int NWIN = 8 + K - 1;

    __shared__ float2 sIn[CICH][PH][PWS];   // duplicated (v,v) pairs
    __shared__ float2 sW[CICH][KK][17];     // 16 co-pairs + pad (stride 17 pairs)

    const float coef = g_coef[eIdx];
    if (!first && coef == 0.0f) return;     // expert never selected -> no-op

    const int t       = threadIdx.x;
    const int b       = blockIdx.z >> 1;
    const int coBase  = (blockIdx.z & 1) * 32;
    const int tileY   = blockIdx.y * 16;
    const int tileX   = blockIdx.x * 16;

    const int cg      = t >> 5;         // warp-uniform
    const int row     = (t >> 1) & 15;
    const int half    = t & 1;
    const int colBase = half * 8;

    u64 acc[8][2];
#pragma unroll
    for (int p = 0; p < 8; p++) { acc[p][0] = 0ull; acc[p][1] = 0ull; }

    const float* xb = x + (size_t)b * 64 * 65536;

    for (int ciBase = 0; ciBase < 64; ciBase += CICH) {
        __syncthreads();
        // ---- stage input tile (zero-padded, duplicated pairs) ----
        for (int i = t; i < CICH * PH * PW; i += 256) {
            const int cc  = i / (PH * PW);
            const int rem = i - cc * (PH * PW);
            const int r   = rem / PW;
            const int c   = rem - r * PW;
            const int gy  = tileY + r - PAD;
            const int gx  = tileX + c - PAD;
            float v = 0.0f;
            if ((unsigned)gy < 256u && (unsigned)gx < 256u)
                v = xb[(size_t)(ciBase + cc) * 65536 + gy * 256 + gx];
            sIn[cc][r][c] = make_float2(v, v);
        }
        // ---- stage weights as co-pairs: sW[cc][q][cp] = (w[co_even], w[co_odd]) ----
        for (int i = t; i < CICH * 16 * KK; i += 256) {
            const int q   = i % KK;
            const int cp  = (i / KK) & 15;
            const int cc  = i / (16 * KK);
            const int co0 = coBase + 2 * cp;
            const float* wp = w + ((size_t)co0 * 64 + (ciBase + cc)) * KK + q;
            sW[cc][q][cp] = make_float2(wp[0], wp[64 * KK]);
        }
        __syncthreads();

        // ---- compute ----
        for (int cc = 0; cc < CICH; cc++) {
#pragma unroll 1
            for (int dy = 0; dy < K; dy++) {
                u64 win[NWIN];
#pragma unroll
                for (int i = 0; i < NWIN; i++)
                    win[i] = *reinterpret_cast<const u64*>(&sIn[cc][row + dy][colBase + i]);
#pragma unroll
                for (int dx = 0; dx < K; dx++) {
                    const u64 w0 = *reinterpret_cast<const u64*>(&sW[cc][dy * K + dx][cg * 2 + 0]);
                    const u64 w1 = *reinterpret_cast<const u64*>(&sW[cc][dy * K + dx][cg * 2 + 1]);
#pragma unroll
                    for (int p = 0; p < 8; p++) {
                        acc[p][0] = ffma2(win[p + dx], w0, acc[p][0]);
                        acc[p][1] = ffma2(win[p + dx], w1, acc[p][1]);
                    }
                }
            }
        }
    }

    // ---- epilogue: bias -> sigmoid -> out (+=) coef * attn * x ----
    const int gy     = tileY + row;
    const int gxBase = tileX + colBase;
#pragma unroll
    for (int cp = 0; cp < 2; cp++) {
#pragma unroll
        for (int j = 0; j < 2; j++) {
            const int co = coBase + cg * 4 + cp * 2 + j;
            const float bv = bias[co];
            const size_t base = ((size_t)(b * 64 + co) * 256 + gy) * 256 + gxBase;
            float xs[8], os[8], rs[8];
            *reinterpret_cast<float4*>(xs)     = *reinterpret_cast<const float4*>(x + base);
            *reinterpret_cast<float4*>(xs + 4) = *reinterpret_cast<const float4*>(x + base + 4);
            if (first) {
#pragma unroll
                for (int p = 0; p < 8; p++) os[p] = 0.0f;
            } else {
                *reinterpret_cast<float4*>(os)     = *reinterpret_cast<const float4*>(out + base);
                *reinterpret_cast<float4*>(os + 4) = *reinterpret_cast<const float4*>(out + base + 4);
            }
#pragma unroll
            for (int p = 0; p < 8; p++) {
                const float2 a = u2f(acc[p][cp]);
                const float y = (j == 0 ? a.x : a.y) + bv;
                const float attn = 1.0f / (1.0f + __expf(-y));
                rs[p] = os[p] + coef * (attn * xs[p]);
            }
            *reinterpret_cast<float4*>(out + base)     = *reinterpret_cast<const float4*>(rs);
            *reinterpret_cast<float4*>(out + base + 4) = *reinterpret_cast<const float4*>(rs + 4);
        }
    }
}

// ---------------- launcher ----------------
extern "C" void kernel_launch(void* const* d_in, const int* in_sizes, int n_in,
                              void* d_out, int out_size) {
    (void)in_sizes; (void)n_in;
    const float* x    = (const float*)d_in[0];
    const float* gw1  = (const float*)d_in[1];
    const float* gb1  = (const float*)d_in[2];
    const float* gw2  = (const float*)d_in[3];
    const float* gb2  = (const float*)d_in[4];
    const float* ew1  = (const float*)d_in[5];
    const float* eb1  = (const float*)d_in[6];
    const float* ew3  = (const float*)d_in[7];
    const float* eb3  = (const float*)d_in[8];
    const float* ew7  = (const float*)d_in[9];
    const float* eb7  = (const float*)d_in[10];
    const float* ew11 = (const float*)d_in[11];
    const float* eb11 = (const float*)d_in[12];
    float* out = (float*)d_out;

    // Output layout: [8,64,256,256] tensor = 33,554,432 floats, then the scalar
    // loss as the LAST element. Use out_size so the offset can't be wrong again.
    float* lossPtr = out + (size_t)(out_size - 1);

    avgpool_kernel<<<512, 256>>>(x);
    gating_kernel<<<1, 256>>>(gw1, gb1, gw2, gb2, lossPtr);

    dim3 grid(16, 16, 16);  // (W/16, H/16, B * 2 co-halves)
    conv_expert<1, 16><<<grid, 256>>>(x, ew1,  eb1,  0, out, 1);
    conv_expert<3,  8><<<grid, 256>>>(x, ew3,  eb3,  1, out, 0);
    conv_expert<7,  4><<<grid, 256>>>(x, ew7,  eb7,  2, out, 0);
    conv_expert<11, 2><<<grid, 256>>>(x, ew11, eb11, 3, out, 0);
}